// round 1
// baseline (speedup 1.0000x reference)
#include <cuda_runtime.h>
#include <math.h>

// Problem constants
#define BSZ 4
#define SEQ 2048
#define DMODEL 1024
#define NH 16
#define DKH 64
#define MROWS (BSZ * SEQ)   // 8192

// ---------------------------------------------------------------------------
// Scratch (device globals: allocation-free rule)
// ---------------------------------------------------------------------------
__device__ float g_Qp[(size_t)MROWS * DMODEL];
__device__ float g_Kp[(size_t)MROWS * DMODEL];
__device__ float g_Vp[(size_t)MROWS * DMODEL];
__device__ float g_At[(size_t)MROWS * DMODEL];

// ---------------------------------------------------------------------------
// GEMM: C[M,N] = A[M,K] @ B[N,K]^T + bias[N]
// 128x128 block tile, BK=8, 256 threads, 8x8 per-thread micro-tile.
// M,N divisible by 128, K divisible by 8 (true here: 8192/1024/1024).
// ---------------------------------------------------------------------------
__global__ __launch_bounds__(256) void gemm_bias_kernel(
    const float* __restrict__ A, const float* __restrict__ B,
    const float* __restrict__ bias, float* __restrict__ C,
    int Mdim, int Ndim, int Kdim)
{
    __shared__ float As[8][128];
    __shared__ float Bs[8][128];

    const int t   = threadIdx.x;
    const int tr  = t >> 4;        // 0..15 (row group)
    const int tc  = t & 15;        // 0..15 (col group)
    const int brow = blockIdx.y * 128;
    const int bcol = blockIdx.x * 128;

    const int lr = t >> 1;         // 0..127 tile row for loading
    const int lk = (t & 1) << 2;   // 0 or 4

    const float* Aptr = A + (size_t)(brow + lr) * Kdim + lk;
    const float* Bptr = B + (size_t)(bcol + lr) * Kdim + lk;

    float acc[8][8];
#pragma unroll
    for (int i = 0; i < 8; ++i)
#pragma unroll
        for (int j = 0; j < 8; ++j) acc[i][j] = 0.f;

    for (int k0 = 0; k0 < Kdim; k0 += 8) {
        float4 av = *(const float4*)(Aptr + k0);
        float4 bv = *(const float4*)(Bptr + k0);
        As[lk + 0][lr] = av.x; As[lk + 1][lr] = av.y;
        As[lk + 2][lr] = av.z; As[lk + 3][lr] = av.w;
        Bs[lk + 0][lr] = bv.x; Bs[lk + 1][lr] = bv.y;
        Bs[lk + 2][lr] = bv.z; Bs[lk + 3][lr] = bv.w;
        __syncthreads();

#pragma unroll
        for (int kk = 0; kk < 8; ++kk) {
            float a[8], b[8];
            *(float4*)(a)     = *(const float4*)&As[kk][tr * 8];
            *(float4*)(a + 4) = *(const float4*)&As[kk][tr * 8 + 4];
            *(float4*)(b)     = *(const float4*)&Bs[kk][tc * 8];
            *(float4*)(b + 4) = *(const float4*)&Bs[kk][tc * 8 + 4];
#pragma unroll
            for (int i = 0; i < 8; ++i)
#pragma unroll
                for (int j = 0; j < 8; ++j)
                    acc[i][j] = fmaf(a[i], b[j], acc[i][j]);
        }
        __syncthreads();
    }

    float bb[8];
#pragma unroll
    for (int j = 0; j < 8; ++j) bb[j] = bias[bcol + tc * 8 + j];

#pragma unroll
    for (int i = 0; i < 8; ++i) {
        float* Crow = C + (size_t)(brow + tr * 8 + i) * Ndim + bcol + tc * 8;
        float4 o0 = make_float4(acc[i][0] + bb[0], acc[i][1] + bb[1],
                                acc[i][2] + bb[2], acc[i][3] + bb[3]);
        float4 o1 = make_float4(acc[i][4] + bb[4], acc[i][5] + bb[5],
                                acc[i][6] + bb[6], acc[i][7] + bb[7]);
        *(float4*)(Crow)     = o0;
        *(float4*)(Crow + 4) = o1;
    }
}

// ---------------------------------------------------------------------------
// Flash attention: per block = one (b, h) and 64 q rows; DK=64 resident.
// Online softmax with -1e30 sentinel for masked keys (annihilated by the
// running-max rescale exactly as the reference NEG/zeroing does).
// Masked q rows are written as 0 (reference zeros attn there).
// Thread layout: 256 threads; thread t owns row r = t>>2 and 16 columns
// c = j4*16 + (t&3)*4 + e  (4 contiguous float4 chunks -> conflict-free LDS).
// ---------------------------------------------------------------------------
#define ATT_SMEM_FLOATS (64 * 65 + 64 * 68 + 64 * 68 + 64 * 65)
#define ATT_SMEM_BYTES  (ATT_SMEM_FLOATS * 4 + 64 * 4)

__global__ __launch_bounds__(256) void attn_kernel(
    const float* __restrict__ Q, const float* __restrict__ K,
    const float* __restrict__ V, const int* __restrict__ mask,
    float* __restrict__ O)
{
    extern __shared__ float sm[];
    float* Qs  = sm;                 // [64][65]  row-major (q row, dk)
    float* Kst = Qs + 64 * 65;       // [64][68]  transposed (dk, kpos)
    float* Vs  = Kst + 64 * 68;      // [64][68]  row-major (kpos, dk)
    float* Ps  = Vs + 64 * 68;       // [64][65]  probabilities
    int*   mk  = (int*)(Ps + 64 * 65); // [64] key mask

    const int t  = threadIdx.x;
    const int b  = blockIdx.z;
    const int h  = blockIdx.y;
    const int q0 = blockIdx.x * 64;
    const size_t baseBH = (size_t)b * SEQ * DMODEL + (size_t)h * DKH;

    // Load Q tile (64 x 64)
#pragma unroll
    for (int it = 0; it < 4; ++it) {
        int f   = t + it * 256;
        int row = f >> 4;
        int c4  = (f & 15) << 2;
        float4 v = *(const float4*)(Q + baseBH + (size_t)(q0 + row) * DMODEL + c4);
        Qs[row * 65 + c4 + 0] = v.x;
        Qs[row * 65 + c4 + 1] = v.y;
        Qs[row * 65 + c4 + 2] = v.z;
        Qs[row * 65 + c4 + 3] = v.w;
    }

    const int r  = t >> 2;
    const int cq = t & 3;

    float m = -1e30f, l = 0.f;
    float acc[16];
#pragma unroll
    for (int j = 0; j < 16; ++j) acc[j] = 0.f;

    for (int k0 = 0; k0 < SEQ; k0 += 64) {
        // Load K (transposed) and V tiles
#pragma unroll
        for (int it = 0; it < 4; ++it) {
            int f   = t + it * 256;
            int row = f >> 4;
            int c4  = (f & 15) << 2;
            float4 kv = *(const float4*)(K + baseBH + (size_t)(k0 + row) * DMODEL + c4);
            Kst[(c4 + 0) * 68 + row] = kv.x;
            Kst[(c4 + 1) * 68 + row] = kv.y;
            Kst[(c4 + 2) * 68 + row] = kv.z;
            Kst[(c4 + 3) * 68 + row] = kv.w;
            float4 vv = *(const float4*)(V + baseBH + (size_t)(k0 + row) * DMODEL + c4);
            Vs[row * 68 + c4 + 0] = vv.x;
            Vs[row * 68 + c4 + 1] = vv.y;
            Vs[row * 68 + c4 + 2] = vv.z;
            Vs[row * 68 + c4 + 3] = vv.w;
        }
        if (t < 64) mk[t] = mask[(size_t)b * SEQ + k0 + t];
        __syncthreads();

        // Scores: sv[c] = Q[r,:] . K[c,:]
        float sv[16];
#pragma unroll
        for (int j = 0; j < 16; ++j) sv[j] = 0.f;
#pragma unroll 8
        for (int kk = 0; kk < 64; ++kk) {
            float qv = Qs[r * 65 + kk];
#pragma unroll
            for (int j4 = 0; j4 < 4; ++j4) {
                const float4 kw = *(const float4*)&Kst[kk * 68 + j4 * 16 + cq * 4];
                sv[j4 * 4 + 0] = fmaf(qv, kw.x, sv[j4 * 4 + 0]);
                sv[j4 * 4 + 1] = fmaf(qv, kw.y, sv[j4 * 4 + 1]);
                sv[j4 * 4 + 2] = fmaf(qv, kw.z, sv[j4 * 4 + 2]);
                sv[j4 * 4 + 3] = fmaf(qv, kw.w, sv[j4 * 4 + 3]);
            }
        }

        // Scale + key mask; tile row-max
        float mloc = -1e30f;
#pragma unroll
        for (int j4 = 0; j4 < 4; ++j4)
#pragma unroll
            for (int e = 0; e < 4; ++e) {
                int c = j4 * 16 + cq * 4 + e;
                float s = mk[c] ? sv[j4 * 4 + e] * 0.125f : -1e30f;
                sv[j4 * 4 + e] = s;
                mloc = fmaxf(mloc, s);
            }
        mloc = fmaxf(mloc, __shfl_xor_sync(0xffffffffu, mloc, 1));
        mloc = fmaxf(mloc, __shfl_xor_sync(0xffffffffu, mloc, 2));

        float mnew = fmaxf(m, mloc);
        float sc   = __expf(m - mnew);
        float lloc = 0.f;
#pragma unroll
        for (int j4 = 0; j4 < 4; ++j4)
#pragma unroll
            for (int e = 0; e < 4; ++e) {
                int c = j4 * 16 + cq * 4 + e;
                float p = __expf(sv[j4 * 4 + e] - mnew);
                Ps[r * 65 + c] = p;
                lloc += p;
            }
        lloc += __shfl_xor_sync(0xffffffffu, lloc, 1);
        lloc += __shfl_xor_sync(0xffffffffu, lloc, 2);
        l = l * sc + lloc;
        m = mnew;
#pragma unroll
        for (int j = 0; j < 16; ++j) acc[j] *= sc;
        __syncthreads();

        // O += P @ V
#pragma unroll 8
        for (int jj = 0; jj < 64; ++jj) {
            float p = Ps[r * 65 + jj];
#pragma unroll
            for (int j4 = 0; j4 < 4; ++j4) {
                const float4 vv = *(const float4*)&Vs[jj * 68 + j4 * 16 + cq * 4];
                acc[j4 * 4 + 0] = fmaf(p, vv.x, acc[j4 * 4 + 0]);
                acc[j4 * 4 + 1] = fmaf(p, vv.y, acc[j4 * 4 + 1]);
                acc[j4 * 4 + 2] = fmaf(p, vv.z, acc[j4 * 4 + 2]);
                acc[j4 * 4 + 3] = fmaf(p, vv.w, acc[j4 * 4 + 3]);
            }
        }
        __syncthreads();
    }

    const int qi = q0 + r;
    const int mq = mask[(size_t)b * SEQ + qi];
    const float inv = (mq != 0 && l > 0.f) ? (1.f / l) : 0.f;
    float* Orow = O + baseBH + (size_t)qi * DMODEL;
#pragma unroll
    for (int j4 = 0; j4 < 4; ++j4) {
        float4 o = make_float4(acc[j4 * 4 + 0] * inv, acc[j4 * 4 + 1] * inv,
                               acc[j4 * 4 + 2] * inv, acc[j4 * 4 + 3] * inv);
        *(float4*)(Orow + j4 * 16 + cq * 4) = o;
    }
}

// ---------------------------------------------------------------------------
// Launch
// ---------------------------------------------------------------------------
extern "C" void kernel_launch(void* const* d_in, const int* in_sizes, int n_in,
                              void* d_out, int out_size)
{
    const float* q    = (const float*)d_in[0];
    const float* k    = (const float*)d_in[1];
    const float* v    = (const float*)d_in[2];
    const int*   mask = (const int*)  d_in[3];
    const float* Wq   = (const float*)d_in[4];
    const float* bq   = (const float*)d_in[5];
    const float* Wk   = (const float*)d_in[6];
    const float* bk   = (const float*)d_in[7];
    const float* Wv   = (const float*)d_in[8];
    const float* bv   = (const float*)d_in[9];
    const float* Wo   = (const float*)d_in[10];
    const float* bo   = (const float*)d_in[11];
    float* out = (float*)d_out;

    float *Qp, *Kp, *Vp, *At;
    cudaGetSymbolAddress((void**)&Qp, g_Qp);
    cudaGetSymbolAddress((void**)&Kp, g_Kp);
    cudaGetSymbolAddress((void**)&Vp, g_Vp);
    cudaGetSymbolAddress((void**)&At, g_At);

    cudaFuncSetAttribute(attn_kernel,
                         cudaFuncAttributeMaxDynamicSharedMemorySize,
                         ATT_SMEM_BYTES);

    dim3 gGemm(DMODEL / 128, MROWS / 128);  // (8, 64)
    gemm_bias_kernel<<<gGemm, 256>>>(q, Wq, bq, Qp, MROWS, DMODEL, DMODEL);
    gemm_bias_kernel<<<gGemm, 256>>>(k, Wk, bk, Kp, MROWS, DMODEL, DMODEL);
    gemm_bias_kernel<<<gGemm, 256>>>(v, Wv, bv, Vp, MROWS, DMODEL, DMODEL);

    dim3 gAttn(SEQ / 64, NH, BSZ);          // (32, 16, 4)
    attn_kernel<<<gAttn, 256, ATT_SMEM_BYTES>>>(Qp, Kp, Vp, mask, At);

    gemm_bias_kernel<<<gGemm, 256>>>(At, Wo, bo, out, MROWS, DMODEL, DMODEL);
}

// round 7
// speedup vs baseline: 2.0195x; 2.0195x over previous
#include <cuda_runtime.h>
#include <cuda_bf16.h>
#include <cstdint>
#include <math.h>

#define BSZ 4
#define SEQ 2048
#define DMODEL 1024
#define NH 16
#define DKH 64
#define MROWS (BSZ * SEQ)   // 8192

// ---------------------------------------------------------------------------
// Scratch (device globals: allocation-free rule)
// ---------------------------------------------------------------------------
__device__ float g_Qp[(size_t)MROWS * DMODEL];
__device__ float g_Kp[(size_t)MROWS * DMODEL];
__device__ float g_Vp[(size_t)MROWS * DMODEL];
__device__ float g_At[(size_t)MROWS * DMODEL];
__device__ __nv_bfloat16 g_ah[(size_t)MROWS * DMODEL];
__device__ __nv_bfloat16 g_al[(size_t)MROWS * DMODEL];
__device__ __nv_bfloat16 g_wh[(size_t)DMODEL * DMODEL];
__device__ __nv_bfloat16 g_wl[(size_t)DMODEL * DMODEL];

// ---------------------------------------------------------------------------
// Warp MMA helpers (PTX sm_80-level: valid under virtual compute_103)
// ---------------------------------------------------------------------------
__device__ __forceinline__ uint32_t smem_u32(const void* p) {
    uint32_t a;
    asm("{ .reg .u64 t; cvta.to.shared.u64 t, %1; cvt.u32.u64 %0, t; }"
        : "=r"(a) : "l"(p));
    return a;
}
#define LDSM_X4(r, addr) \
    asm volatile("ldmatrix.sync.aligned.m8n8.x4.shared.b16 {%0,%1,%2,%3}, [%4];" \
        : "=r"((r)[0]), "=r"((r)[1]), "=r"((r)[2]), "=r"((r)[3]) : "r"(addr))
#define LDSM_X2(r, addr) \
    asm volatile("ldmatrix.sync.aligned.m8n8.x2.shared.b16 {%0,%1}, [%2];" \
        : "=r"((r)[0]), "=r"((r)[1]) : "r"(addr))
#define MMA16816(c, a, b) \
    asm volatile("mma.sync.aligned.m16n8k16.row.col.f32.bf16.bf16.f32 " \
        "{%0,%1,%2,%3}, {%4,%5,%6,%7}, {%8,%9}, {%0,%1,%2,%3};" \
        : "+f"((c)[0]), "+f"((c)[1]), "+f"((c)[2]), "+f"((c)[3]) \
        : "r"((a)[0]), "r"((a)[1]), "r"((a)[2]), "r"((a)[3]), \
          "r"((b)[0]), "r"((b)[1]))

// ---------------------------------------------------------------------------
// Split fp32 -> (hi, lo) bf16:  x = hi + lo + O(2^-18 x)
// ---------------------------------------------------------------------------
__global__ __launch_bounds__(256) void split_kernel(
    const float4* __restrict__ x, __nv_bfloat16* __restrict__ hi,
    __nv_bfloat16* __restrict__ lo, int n4)
{
    int i = blockIdx.x * blockDim.x + threadIdx.x;
    if (i >= n4) return;
    float4 v = x[i];
    union { __nv_bfloat16 b[4]; uint2 u; } H, L;
    H.b[0] = __float2bfloat16(v.x); L.b[0] = __float2bfloat16(v.x - __bfloat162float(H.b[0]));
    H.b[1] = __float2bfloat16(v.y); L.b[1] = __float2bfloat16(v.y - __bfloat162float(H.b[1]));
    H.b[2] = __float2bfloat16(v.z); L.b[2] = __float2bfloat16(v.z - __bfloat162float(H.b[2]));
    H.b[3] = __float2bfloat16(v.w); L.b[3] = __float2bfloat16(v.w - __bfloat162float(H.b[3]));
    *reinterpret_cast<uint2*>(hi + (size_t)i * 4) = H.u;
    *reinterpret_cast<uint2*>(lo + (size_t)i * 4) = L.u;
}

// ---------------------------------------------------------------------------
// HMMA GEMM: C[8192,1024] = A @ B^T + bias, A/B as bf16 hi/lo splits.
// D = Ah*Bh + Ah*Bl + Al*Bh in fp32 accum (error-compensated).
// CTA 128x128, 8 warps (warp tile 64x32), BK=32 double-buffered smem.
// Smem rows padded to 40 bf16 (80B): ldmatrix phases hit all 32 banks once.
// ---------------------------------------------------------------------------
#define GPAD 40
#define GTILE (128 * GPAD)               // bf16 elems per tile
#define GSTAGE (4 * GTILE)               // Ah,Al,Bh,Bl
#define GSM_BYTES (2 * GSTAGE * 2)       // 2 stages, bf16 -> 81920 B

__global__ __launch_bounds__(256) void gemm_mma_kernel(
    const __nv_bfloat16* __restrict__ Ah, const __nv_bfloat16* __restrict__ Al,
    const __nv_bfloat16* __restrict__ Bh, const __nv_bfloat16* __restrict__ Bl,
    const float* __restrict__ bias, float* __restrict__ C)
{
    extern __shared__ __align__(16) __nv_bfloat16 sm[];
    const int tid  = threadIdx.x;
    const int wid  = tid >> 5;
    const int lane = tid & 31;
    const int brow = blockIdx.y * 128, bcol = blockIdx.x * 128;
    const int wm   = (wid & 1) * 64;     // warp row offset in CTA tile
    const int wn   = (wid >> 1) * 32;    // warp col offset

    const uint32_t sbase = smem_u32(sm);

    // Per-thread gmem load coords: idx = tid + it*256 -> row=idx>>2, seg=idx&3
    const int lr0 = tid >> 2, ls0 = (tid & 3) * 8;

    const __nv_bfloat16* srcs[4] = {Ah, Al, Bh, Bl};
    const int rb[4] = {brow, brow, bcol, bcol};

    // Prologue: chunk 0 -> stage 0
#pragma unroll
    for (int t = 0; t < 4; ++t) {
#pragma unroll
        for (int it = 0; it < 2; ++it) {
            int row = lr0 + it * 64;
            uint4 v = *reinterpret_cast<const uint4*>(
                srcs[t] + (size_t)(rb[t] + row) * DMODEL + ls0);
            *reinterpret_cast<uint4*>(sm + t * GTILE + row * GPAD + ls0) = v;
        }
    }
    __syncthreads();

    float acc[4][4][4];
#pragma unroll
    for (int i = 0; i < 4; ++i)
#pragma unroll
        for (int j = 0; j < 4; ++j)
#pragma unroll
            for (int e = 0; e < 4; ++e) acc[i][j][e] = 0.f;

    // ldmatrix per-thread row/col pieces
    const int arow = wm + (lane & 15);
    const int acol = (lane >> 4) * 8;
    const int brw  = wn + (lane & 7);
    const int bcl  = ((lane >> 3) & 1) * 8;

    for (int c = 0; c < DMODEL / 32; ++c) {
        const int st = c & 1;
        // Issue next chunk's global loads (latency hidden under MMA)
        uint4 nxt[8];
        if (c + 1 < DMODEL / 32) {
#pragma unroll
            for (int t = 0; t < 4; ++t)
#pragma unroll
                for (int it = 0; it < 2; ++it) {
                    int row = lr0 + it * 64;
                    nxt[t * 2 + it] = *reinterpret_cast<const uint4*>(
                        srcs[t] + (size_t)(rb[t] + row) * DMODEL + (c + 1) * 32 + ls0);
                }
        }

        const uint32_t stOff = sbase + st * (GSTAGE * 2);
#pragma unroll
        for (int ks = 0; ks < 2; ++ks) {
            uint32_t ah[4][4], al[4][4], bh[4][2], bl[4][2];
#pragma unroll
            for (int mt = 0; mt < 4; ++mt) {
                uint32_t ra = stOff + 2 * ((arow + mt * 16) * GPAD + ks * 16 + acol);
                LDSM_X4(ah[mt], ra);
                LDSM_X4(al[mt], ra + 2 * GTILE);
            }
#pragma unroll
            for (int nt = 0; nt < 4; ++nt) {
                uint32_t rbADDR = stOff + 2 * (2 * GTILE + (brw + nt * 8) * GPAD + ks * 16 + bcl);
                LDSM_X2(bh[nt], rbADDR);
                LDSM_X2(bl[nt], rbADDR + 2 * GTILE);
            }
#pragma unroll
            for (int mt = 0; mt < 4; ++mt)
#pragma unroll
                for (int nt = 0; nt < 4; ++nt) {
                    MMA16816(acc[mt][nt], ah[mt], bh[nt]);
                    MMA16816(acc[mt][nt], ah[mt], bl[nt]);
                    MMA16816(acc[mt][nt], al[mt], bh[nt]);
                }
        }

        if (c + 1 < DMODEL / 32) {
            __nv_bfloat16* dst = sm + (st ^ 1) * GSTAGE;
#pragma unroll
            for (int t = 0; t < 4; ++t)
#pragma unroll
                for (int it = 0; it < 2; ++it) {
                    int row = lr0 + it * 64;
                    *reinterpret_cast<uint4*>(dst + t * GTILE + row * GPAD + ls0) =
                        nxt[t * 2 + it];
                }
        }
        __syncthreads();
    }

    // Epilogue: write C with bias. Fragment map: rows groupID/groupID+8,
    // cols 2*(lane&3), per m16n8 tile.
    const int gid = lane >> 2, tig = lane & 3;
#pragma unroll
    for (int mt = 0; mt < 4; ++mt) {
#pragma unroll
        for (int nt = 0; nt < 4; ++nt) {
            int col = bcol + wn + nt * 8 + tig * 2;
            float2 bv = *reinterpret_cast<const float2*>(bias + col);
            int row0 = brow + wm + mt * 16 + gid;
            float2 o0 = make_float2(acc[mt][nt][0] + bv.x, acc[mt][nt][1] + bv.y);
            float2 o1 = make_float2(acc[mt][nt][2] + bv.x, acc[mt][nt][3] + bv.y);
            *reinterpret_cast<float2*>(C + (size_t)row0 * DMODEL + col) = o0;
            *reinterpret_cast<float2*>(C + (size_t)(row0 + 8) * DMODEL + col) = o1;
        }
    }
}

// ---------------------------------------------------------------------------
// Flash attention: tile 128 q x 64 k, DK=64 resident; 256 threads.
// Thread t: rows r0=2*(t>>2), r0+1; cols j4*16 + (t&3)*4 + e (16 cols).
// ---------------------------------------------------------------------------
#define ATT_SMEM_BYTES ((128 * 65 + 64 * 68 + 64 * 68 + 128 * 65) * 4 + 64 * 4)

__global__ __launch_bounds__(256, 2) void attn_kernel(
    const float* __restrict__ Q, const float* __restrict__ K,
    const float* __restrict__ V, const int* __restrict__ mask,
    float* __restrict__ O)
{
    extern __shared__ float smf[];
    float* Qs  = smf;                   // [128][65]
    float* Kst = Qs + 128 * 65;         // [64 dk][68 kpos] transposed
    float* Vs  = Kst + 64 * 68;         // [64 kpos][68 dk]
    float* Ps  = Vs + 64 * 68;          // [128][65]
    int*   mk  = (int*)(Ps + 128 * 65); // [64]

    const int t  = threadIdx.x;
    const int b  = blockIdx.z;
    const int h  = blockIdx.y;
    const int q0 = blockIdx.x * 128;
    const size_t baseBH = (size_t)b * SEQ * DMODEL + (size_t)h * DKH;

#pragma unroll
    for (int it = 0; it < 8; ++it) {
        int f = t + it * 256;
        int row = f >> 4, c4 = (f & 15) << 2;
        float4 v = *(const float4*)(Q + baseBH + (size_t)(q0 + row) * DMODEL + c4);
        Qs[row * 65 + c4 + 0] = v.x; Qs[row * 65 + c4 + 1] = v.y;
        Qs[row * 65 + c4 + 2] = v.z; Qs[row * 65 + c4 + 3] = v.w;
    }

    const int cq = t & 3;
    const int r0 = (t >> 2) * 2;
    const int r1 = r0 + 1;

    float m0 = -1e30f, m1 = -1e30f, l0 = 0.f, l1 = 0.f;
    float acc0[16], acc1[16];
#pragma unroll
    for (int j = 0; j < 16; ++j) { acc0[j] = 0.f; acc1[j] = 0.f; }

    for (int k0 = 0; k0 < SEQ; k0 += 64) {
#pragma unroll
        for (int it = 0; it < 4; ++it) {
            int f = t + it * 256;
            int row = f >> 4, c4 = (f & 15) << 2;
            float4 kv = *(const float4*)(K + baseBH + (size_t)(k0 + row) * DMODEL + c4);
            Kst[(c4 + 0) * 68 + row] = kv.x;
            Kst[(c4 + 1) * 68 + row] = kv.y;
            Kst[(c4 + 2) * 68 + row] = kv.z;
            Kst[(c4 + 3) * 68 + row] = kv.w;
            float4 vv = *(const float4*)(V + baseBH + (size_t)(k0 + row) * DMODEL + c4);
            Vs[row * 68 + c4 + 0] = vv.x; Vs[row * 68 + c4 + 1] = vv.y;
            Vs[row * 68 + c4 + 2] = vv.z; Vs[row * 68 + c4 + 3] = vv.w;
        }
        if (t < 64) mk[t] = mask[(size_t)b * SEQ + k0 + t];
        __syncthreads();

        float sv0[16], sv1[16];
#pragma unroll
        for (int j = 0; j < 16; ++j) { sv0[j] = 0.f; sv1[j] = 0.f; }
#pragma unroll 4
        for (int kk = 0; kk < 64; ++kk) {
            float qa = Qs[r0 * 65 + kk];
            float qb = Qs[r1 * 65 + kk];
#pragma unroll
            for (int j4 = 0; j4 < 4; ++j4) {
                const float4 kw = *(const float4*)&Kst[kk * 68 + j4 * 16 + cq * 4];
                sv0[j4 * 4 + 0] = fmaf(qa, kw.x, sv0[j4 * 4 + 0]);
                sv0[j4 * 4 + 1] = fmaf(qa, kw.y, sv0[j4 * 4 + 1]);
                sv0[j4 * 4 + 2] = fmaf(qa, kw.z, sv0[j4 * 4 + 2]);
                sv0[j4 * 4 + 3] = fmaf(qa, kw.w, sv0[j4 * 4 + 3]);
                sv1[j4 * 4 + 0] = fmaf(qb, kw.x, sv1[j4 * 4 + 0]);
                sv1[j4 * 4 + 1] = fmaf(qb, kw.y, sv1[j4 * 4 + 1]);
                sv1[j4 * 4 + 2] = fmaf(qb, kw.z, sv1[j4 * 4 + 2]);
                sv1[j4 * 4 + 3] = fmaf(qb, kw.w, sv1[j4 * 4 + 3]);
            }
        }

        float ma = -1e30f, mb = -1e30f;
#pragma unroll
        for (int j4 = 0; j4 < 4; ++j4)
#pragma unroll
            for (int e = 0; e < 4; ++e) {
                int cidx = j4 * 16 + cq * 4 + e;
                float s0 = mk[cidx] ? sv0[j4 * 4 + e] * 0.125f : -1e30f;
                float s1 = mk[cidx] ? sv1[j4 * 4 + e] * 0.125f : -1e30f;
                sv0[j4 * 4 + e] = s0; sv1[j4 * 4 + e] = s1;
                ma = fmaxf(ma, s0); mb = fmaxf(mb, s1);
            }
        ma = fmaxf(ma, __shfl_xor_sync(0xffffffffu, ma, 1));
        ma = fmaxf(ma, __shfl_xor_sync(0xffffffffu, ma, 2));
        mb = fmaxf(mb, __shfl_xor_sync(0xffffffffu, mb, 1));
        mb = fmaxf(mb, __shfl_xor_sync(0xffffffffu, mb, 2));

        float mn0 = fmaxf(m0, ma), mn1 = fmaxf(m1, mb);
        float sc0 = __expf(m0 - mn0), sc1 = __expf(m1 - mn1);
        float ll0 = 0.f, ll1 = 0.f;
#pragma unroll
        for (int j4 = 0; j4 < 4; ++j4)
#pragma unroll
            for (int e = 0; e < 4; ++e) {
                int cidx = j4 * 16 + cq * 4 + e;
                float p0 = __expf(sv0[j4 * 4 + e] - mn0);
                float p1 = __expf(sv1[j4 * 4 + e] - mn1);
                Ps[r0 * 65 + cidx] = p0;
                Ps[r1 * 65 + cidx] = p1;
                ll0 += p0; ll1 += p1;
            }
        ll0 += __shfl_xor_sync(0xffffffffu, ll0, 1);
        ll0 += __shfl_xor_sync(0xffffffffu, ll0, 2);
        ll1 += __shfl_xor_sync(0xffffffffu, ll1, 1);
        ll1 += __shfl_xor_sync(0xffffffffu, ll1, 2);
        l0 = l0 * sc0 + ll0; l1 = l1 * sc1 + ll1;
        m0 = mn0; m1 = mn1;
#pragma unroll
        for (int j = 0; j < 16; ++j) { acc0[j] *= sc0; acc1[j] *= sc1; }
        __syncthreads();

#pragma unroll 4
        for (int jj = 0; jj < 64; ++jj) {
            float p0 = Ps[r0 * 65 + jj];
            float p1 = Ps[r1 * 65 + jj];
#pragma unroll
            for (int j4 = 0; j4 < 4; ++j4) {
                const float4 vv = *(const float4*)&Vs[jj * 68 + j4 * 16 + cq * 4];
                acc0[j4 * 4 + 0] = fmaf(p0, vv.x, acc0[j4 * 4 + 0]);
                acc0[j4 * 4 + 1] = fmaf(p0, vv.y, acc0[j4 * 4 + 1]);
                acc0[j4 * 4 + 2] = fmaf(p0, vv.z, acc0[j4 * 4 + 2]);
                acc0[j4 * 4 + 3] = fmaf(p0, vv.w, acc0[j4 * 4 + 3]);
                acc1[j4 * 4 + 0] = fmaf(p1, vv.x, acc1[j4 * 4 + 0]);
                acc1[j4 * 4 + 1] = fmaf(p1, vv.y, acc1[j4 * 4 + 1]);
                acc1[j4 * 4 + 2] = fmaf(p1, vv.z, acc1[j4 * 4 + 2]);
                acc1[j4 * 4 + 3] = fmaf(p1, vv.w, acc1[j4 * 4 + 3]);
            }
        }
        __syncthreads();
    }

    const int qi0 = q0 + r0, qi1 = q0 + r1;
    const int mq0 = mask[(size_t)b * SEQ + qi0];
    const int mq1 = mask[(size_t)b * SEQ + qi1];
    const float inv0 = (mq0 != 0 && l0 > 0.f) ? (1.f / l0) : 0.f;
    const float inv1 = (mq1 != 0 && l1 > 0.f) ? (1.f / l1) : 0.f;
    float* O0 = O + baseBH + (size_t)qi0 * DMODEL;
    float* O1 = O + baseBH + (size_t)qi1 * DMODEL;
#pragma unroll
    for (int j4 = 0; j4 < 4; ++j4) {
        *(float4*)(O0 + j4 * 16 + cq * 4) = make_float4(
            acc0[j4 * 4 + 0] * inv0, acc0[j4 * 4 + 1] * inv0,
            acc0[j4 * 4 + 2] * inv0, acc0[j4 * 4 + 3] * inv0);
        *(float4*)(O1 + j4 * 16 + cq * 4) = make_float4(
            acc1[j4 * 4 + 0] * inv1, acc1[j4 * 4 + 1] * inv1,
            acc1[j4 * 4 + 2] * inv1, acc1[j4 * 4 + 3] * inv1);
    }
}

// ---------------------------------------------------------------------------
// Launch
// ---------------------------------------------------------------------------
extern "C" void kernel_launch(void* const* d_in, const int* in_sizes, int n_in,
                              void* d_out, int out_size)
{
    const float* q    = (const float*)d_in[0];
    const float* k    = (const float*)d_in[1];
    const float* v    = (const float*)d_in[2];
    const int*   mask = (const int*)  d_in[3];
    const float* Wq   = (const float*)d_in[4];
    const float* bq   = (const float*)d_in[5];
    const float* Wk   = (const float*)d_in[6];
    const float* bk   = (const float*)d_in[7];
    const float* Wv   = (const float*)d_in[8];
    const float* bv   = (const float*)d_in[9];
    const float* Wo   = (const float*)d_in[10];
    const float* bo   = (const float*)d_in[11];
    float* out = (float*)d_out;

    float *Qp, *Kp, *Vp, *At;
    __nv_bfloat16 *ah, *al, *wh, *wl;
    cudaGetSymbolAddress((void**)&Qp, g_Qp);
    cudaGetSymbolAddress((void**)&Kp, g_Kp);
    cudaGetSymbolAddress((void**)&Vp, g_Vp);
    cudaGetSymbolAddress((void**)&At, g_At);
    cudaGetSymbolAddress((void**)&ah, g_ah);
    cudaGetSymbolAddress((void**)&al, g_al);
    cudaGetSymbolAddress((void**)&wh, g_wh);
    cudaGetSymbolAddress((void**)&wl, g_wl);

    cudaFuncSetAttribute(gemm_mma_kernel,
                         cudaFuncAttributeMaxDynamicSharedMemorySize, GSM_BYTES);
    cudaFuncSetAttribute(attn_kernel,
                         cudaFuncAttributeMaxDynamicSharedMemorySize, ATT_SMEM_BYTES);

    const int nAct4 = MROWS * DMODEL / 4;
    const int nW4   = DMODEL * DMODEL / 4;
    dim3 gGemm(DMODEL / 128, MROWS / 128);      // (8, 64)

    // Q projection
    split_kernel<<<(nAct4 + 255) / 256, 256>>>((const float4*)q, ah, al, nAct4);
    split_kernel<<<(nW4 + 255) / 256, 256>>>((const float4*)Wq, wh, wl, nW4);
    gemm_mma_kernel<<<gGemm, 256, GSM_BYTES>>>(ah, al, wh, wl, bq, Qp);
    // K projection
    split_kernel<<<(nAct4 + 255) / 256, 256>>>((const float4*)k, ah, al, nAct4);
    split_kernel<<<(nW4 + 255) / 256, 256>>>((const float4*)Wk, wh, wl, nW4);
    gemm_mma_kernel<<<gGemm, 256, GSM_BYTES>>>(ah, al, wh, wl, bk, Kp);
    // V projection
    split_kernel<<<(nAct4 + 255) / 256, 256>>>((const float4*)v, ah, al, nAct4);
    split_kernel<<<(nW4 + 255) / 256, 256>>>((const float4*)Wv, wh, wl, nW4);
    gemm_mma_kernel<<<gGemm, 256, GSM_BYTES>>>(ah, al, wh, wl, bv, Vp);

    // Attention
    dim3 gAttn(SEQ / 128, NH, BSZ);             // (16, 16, 4)
    attn_kernel<<<gAttn, 256, ATT_SMEM_BYTES>>>(Qp, Kp, Vp, mask, At);

    // Output projection
    split_kernel<<<(nAct4 + 255) / 256, 256>>>((const float4*)At, ah, al, nAct4);
    split_kernel<<<(nW4 + 255) / 256, 256>>>((const float4*)Wo, wh, wl, nW4);
    gemm_mma_kernel<<<gGemm, 256, GSM_BYTES>>>(ah, al, wh, wl, bo, out);
}

// round 14
// speedup vs baseline: 3.6104x; 1.7878x over previous
#include <cuda_runtime.h>
#include <cuda_bf16.h>
#include <cstdint>
#include <math.h>

#define BSZ 4
#define SEQ 2048
#define DMODEL 1024
#define NH 16
#define DKH 64
#define MROWS (BSZ * SEQ)   // 8192

// ---------------------------------------------------------------------------
// Scratch (device globals: allocation-free rule)
// ---------------------------------------------------------------------------
__device__ float g_Qp[(size_t)MROWS * DMODEL];
__device__ float g_Kp[(size_t)MROWS * DMODEL];
__device__ float g_Vp[(size_t)MROWS * DMODEL];
__device__ float g_At[(size_t)MROWS * DMODEL];
__device__ __nv_bfloat16 g_ah[(size_t)MROWS * DMODEL];
__device__ __nv_bfloat16 g_al[(size_t)MROWS * DMODEL];
__device__ __nv_bfloat16 g_wh[(size_t)DMODEL * DMODEL];
__device__ __nv_bfloat16 g_wl[(size_t)DMODEL * DMODEL];

// ---------------------------------------------------------------------------
// Warp MMA helpers (PTX sm_80-level: valid under virtual compute_103)
// ---------------------------------------------------------------------------
__device__ __forceinline__ uint32_t smem_u32(const void* p) {
    uint32_t a;
    asm("{ .reg .u64 t; cvta.to.shared.u64 t, %1; cvt.u32.u64 %0, t; }"
        : "=r"(a) : "l"(p));
    return a;
}
#define LDSM_X4(r, addr) \
    asm volatile("ldmatrix.sync.aligned.m8n8.x4.shared.b16 {%0,%1,%2,%3}, [%4];" \
        : "=r"((r)[0]), "=r"((r)[1]), "=r"((r)[2]), "=r"((r)[3]) : "r"(addr))
#define LDSM_X2(r, addr) \
    asm volatile("ldmatrix.sync.aligned.m8n8.x2.shared.b16 {%0,%1}, [%2];" \
        : "=r"((r)[0]), "=r"((r)[1]) : "r"(addr))
#define MMA16816(c, a, b) \
    asm volatile("mma.sync.aligned.m16n8k16.row.col.f32.bf16.bf16.f32 " \
        "{%0,%1,%2,%3}, {%4,%5,%6,%7}, {%8,%9}, {%0,%1,%2,%3};" \
        : "+f"((c)[0]), "+f"((c)[1]), "+f"((c)[2]), "+f"((c)[3]) \
        : "r"((a)[0]), "r"((a)[1]), "r"((a)[2]), "r"((a)[3]), \
          "r"((b)[0]), "r"((b)[1]))

// Split x into bf16 hi/lo
__device__ __forceinline__ void bsplit(float x, __nv_bfloat16& h, __nv_bfloat16& l) {
    h = __float2bfloat16(x);
    l = __float2bfloat16(x - __bfloat162float(h));
}
// Pack pair (x->low half, y->high half) with hi/lo split
__device__ __forceinline__ void packsplit2(float x, float y, uint32_t& hi, uint32_t& lo) {
    __nv_bfloat162 H = __floats2bfloat162_rn(x, y);
    float rx = x - __bfloat162float(H.x);
    float ry = y - __bfloat162float(H.y);
    __nv_bfloat162 L = __floats2bfloat162_rn(rx, ry);
    hi = *reinterpret_cast<uint32_t*>(&H);
    lo = *reinterpret_cast<uint32_t*>(&L);
}

// ---------------------------------------------------------------------------
// Split fp32 -> (hi, lo) bf16 arrays (for projection GEMMs)
// ---------------------------------------------------------------------------
__global__ __launch_bounds__(256) void split_kernel(
    const float4* __restrict__ x, __nv_bfloat16* __restrict__ hi,
    __nv_bfloat16* __restrict__ lo, int n4)
{
    int i = blockIdx.x * blockDim.x + threadIdx.x;
    if (i >= n4) return;
    float4 v = x[i];
    union { __nv_bfloat16 b[4]; uint2 u; } H, L;
    bsplit(v.x, H.b[0], L.b[0]);
    bsplit(v.y, H.b[1], L.b[1]);
    bsplit(v.z, H.b[2], L.b[2]);
    bsplit(v.w, H.b[3], L.b[3]);
    *reinterpret_cast<uint2*>(hi + (size_t)i * 4) = H.u;
    *reinterpret_cast<uint2*>(lo + (size_t)i * 4) = L.u;
}

// ---------------------------------------------------------------------------
// HMMA GEMM (verified R7): C = A @ B^T + bias, hi/lo 3-pass compensation.
// ---------------------------------------------------------------------------
#define GPAD 40
#define GTILE (128 * GPAD)
#define GSTAGE (4 * GTILE)
#define GSM_BYTES (2 * GSTAGE * 2)

__global__ __launch_bounds__(256) void gemm_mma_kernel(
    const __nv_bfloat16* __restrict__ Ah, const __nv_bfloat16* __restrict__ Al,
    const __nv_bfloat16* __restrict__ Bh, const __nv_bfloat16* __restrict__ Bl,
    const float* __restrict__ bias, float* __restrict__ C)
{
    extern __shared__ __align__(16) __nv_bfloat16 sm[];
    const int tid  = threadIdx.x;
    const int wid  = tid >> 5;
    const int lane = tid & 31;
    const int brow = blockIdx.y * 128, bcol = blockIdx.x * 128;
    const int wm   = (wid & 1) * 64;
    const int wn   = (wid >> 1) * 32;

    const uint32_t sbase = smem_u32(sm);
    const int lr0 = tid >> 2, ls0 = (tid & 3) * 8;

    const __nv_bfloat16* srcs[4] = {Ah, Al, Bh, Bl};
    const int rb[4] = {brow, brow, bcol, bcol};

#pragma unroll
    for (int t = 0; t < 4; ++t)
#pragma unroll
        for (int it = 0; it < 2; ++it) {
            int row = lr0 + it * 64;
            uint4 v = *reinterpret_cast<const uint4*>(
                srcs[t] + (size_t)(rb[t] + row) * DMODEL + ls0);
            *reinterpret_cast<uint4*>(sm + t * GTILE + row * GPAD + ls0) = v;
        }
    __syncthreads();

    float acc[4][4][4];
#pragma unroll
    for (int i = 0; i < 4; ++i)
#pragma unroll
        for (int j = 0; j < 4; ++j)
#pragma unroll
            for (int e = 0; e < 4; ++e) acc[i][j][e] = 0.f;

    const int arow = wm + (lane & 15);
    const int acol = (lane >> 4) * 8;
    const int brw  = wn + (lane & 7);
    const int bcl  = ((lane >> 3) & 1) * 8;

    for (int c = 0; c < DMODEL / 32; ++c) {
        const int st = c & 1;
        uint4 nxt[8];
        if (c + 1 < DMODEL / 32) {
#pragma unroll
            for (int t = 0; t < 4; ++t)
#pragma unroll
                for (int it = 0; it < 2; ++it) {
                    int row = lr0 + it * 64;
                    nxt[t * 2 + it] = *reinterpret_cast<const uint4*>(
                        srcs[t] + (size_t)(rb[t] + row) * DMODEL + (c + 1) * 32 + ls0);
                }
        }

        const uint32_t stOff = sbase + st * (GSTAGE * 2);
#pragma unroll
        for (int ks = 0; ks < 2; ++ks) {
            uint32_t ah[4][4], al[4][4], bh[4][2], bl[4][2];
#pragma unroll
            for (int mt = 0; mt < 4; ++mt) {
                uint32_t ra = stOff + 2 * ((arow + mt * 16) * GPAD + ks * 16 + acol);
                LDSM_X4(ah[mt], ra);
                LDSM_X4(al[mt], ra + 2 * GTILE);
            }
#pragma unroll
            for (int nt = 0; nt < 4; ++nt) {
                uint32_t rbA = stOff + 2 * (2 * GTILE + (brw + nt * 8) * GPAD + ks * 16 + bcl);
                LDSM_X2(bh[nt], rbA);
                LDSM_X2(bl[nt], rbA + 2 * GTILE);
            }
#pragma unroll
            for (int mt = 0; mt < 4; ++mt)
#pragma unroll
                for (int nt = 0; nt < 4; ++nt) {
                    MMA16816(acc[mt][nt], ah[mt], bh[nt]);
                    MMA16816(acc[mt][nt], ah[mt], bl[nt]);
                    MMA16816(acc[mt][nt], al[mt], bh[nt]);
                }
        }

        if (c + 1 < DMODEL / 32) {
            __nv_bfloat16* dst = sm + (st ^ 1) * GSTAGE;
#pragma unroll
            for (int t = 0; t < 4; ++t)
#pragma unroll
                for (int it = 0; it < 2; ++it) {
                    int row = lr0 + it * 64;
                    *reinterpret_cast<uint4*>(dst + t * GTILE + row * GPAD + ls0) =
                        nxt[t * 2 + it];
                }
        }
        __syncthreads();
    }

    const int gid = lane >> 2, tig = lane & 3;
#pragma unroll
    for (int mt = 0; mt < 4; ++mt)
#pragma unroll
        for (int nt = 0; nt < 4; ++nt) {
            int col = bcol + wn + nt * 8 + tig * 2;
            float2 bv = *reinterpret_cast<const float2*>(bias + col);
            int row0 = brow + wm + mt * 16 + gid;
            float2 o0 = make_float2(acc[mt][nt][0] + bv.x, acc[mt][nt][1] + bv.y);
            float2 o1 = make_float2(acc[mt][nt][2] + bv.x, acc[mt][nt][3] + bv.y);
            *reinterpret_cast<float2*>(C + (size_t)row0 * DMODEL + col) = o0;
            *reinterpret_cast<float2*>(C + (size_t)(row0 + 8) * DMODEL + col) = o1;
        }
}

// ---------------------------------------------------------------------------
// MMA flash attention. CTA = (b, h, 128 q rows); 8 warps x 16-row bands.
// k-tile = 64. QK^T and PV both 3-pass hi/lo compensated mma.sync.
// Smem pad 72 bf16/row (144B): ldmatrix rows tile all 32 banks exactly.
// P fragments built in registers straight from score accumulators.
// ---------------------------------------------------------------------------
#define APAD 72
#define AQH 0
#define AQL (128 * APAD)                  // 9216
#define AKH (2 * 128 * APAD)              // 18432
#define AKL (AKH + 64 * APAD)             // 23040
#define AVH (AKL + 64 * APAD)             // 27648
#define AVL (AVH + 64 * APAD)             // 32256
#define AEND (AVL + 64 * APAD)            // 36864 bf16 elems
#define ATT2_SMEM (AEND * 2 + 64 * 4)     // 73984 B

__global__ __launch_bounds__(256, 1) void attn_mma_kernel(
    const float* __restrict__ Q, const float* __restrict__ K,
    const float* __restrict__ V, const int* __restrict__ mask,
    float* __restrict__ O)
{
    extern __shared__ __align__(16) __nv_bfloat16 sb[];
    int* mk = (int*)(sb + AEND);
    const uint32_t sbase = smem_u32(sb);

    const int t = threadIdx.x, w = t >> 5, lane = t & 31;
    const int b = blockIdx.z, h = blockIdx.y, q0 = blockIdx.x * 128;
    const size_t baseBH = (size_t)b * SEQ * DMODEL + (size_t)h * DKH;

    // Stage Q tile (128x64) as hi/lo bf16
#pragma unroll
    for (int it = 0; it < 8; ++it) {
        int f = t + it * 256;
        int row = f >> 4, c4 = (f & 15) * 4;
        float4 v = *(const float4*)(Q + baseBH + (size_t)(q0 + row) * DMODEL + c4);
        __nv_bfloat16 hh, ll;
        bsplit(v.x, hh, ll); sb[AQH + row * APAD + c4 + 0] = hh; sb[AQL + row * APAD + c4 + 0] = ll;
        bsplit(v.y, hh, ll); sb[AQH + row * APAD + c4 + 1] = hh; sb[AQL + row * APAD + c4 + 1] = ll;
        bsplit(v.z, hh, ll); sb[AQH + row * APAD + c4 + 2] = hh; sb[AQL + row * APAD + c4 + 2] = ll;
        bsplit(v.w, hh, ll); sb[AQH + row * APAD + c4 + 3] = hh; sb[AQL + row * APAD + c4 + 3] = ll;
    }
    __syncthreads();

    // Q fragments (held across the whole loop)
    uint32_t qh[4][4], ql[4][4];
    const int arow = w * 16 + (lane & 15);
    const int acol = (lane >> 4) * 8;
#pragma unroll
    for (int ks = 0; ks < 4; ++ks) {
        uint32_t ra = sbase + 2 * (AQH + arow * APAD + ks * 16 + acol);
        LDSM_X4(qh[ks], ra);
        LDSM_X4(ql[ks], ra + 2 * (AQL - AQH));
    }

    const int gid = lane >> 2, tig = lane & 3;
    const int brw = lane & 7;
    const int bcl = ((lane >> 3) & 1) * 8;

    float m0 = -1e30f, m1 = -1e30f, l0 = 0.f, l1 = 0.f;
    float Oa[8][4];
#pragma unroll
    for (int d = 0; d < 8; ++d)
#pragma unroll
        for (int e = 0; e < 4; ++e) Oa[d][e] = 0.f;

    for (int k0 = 0; k0 < SEQ; k0 += 64) {
        // Load K (row-major) and V (transposed) hi/lo tiles
#pragma unroll
        for (int it = 0; it < 4; ++it) {
            int f = t + it * 256;
            int row = f >> 4, c4 = (f & 15) * 4;   // row = key, c4 = dk
            float4 kv = *(const float4*)(K + baseBH + (size_t)(k0 + row) * DMODEL + c4);
            __nv_bfloat16 hh, ll;
            bsplit(kv.x, hh, ll); sb[AKH + row * APAD + c4 + 0] = hh; sb[AKL + row * APAD + c4 + 0] = ll;
            bsplit(kv.y, hh, ll); sb[AKH + row * APAD + c4 + 1] = hh; sb[AKL + row * APAD + c4 + 1] = ll;
            bsplit(kv.z, hh, ll); sb[AKH + row * APAD + c4 + 2] = hh; sb[AKL + row * APAD + c4 + 2] = ll;
            bsplit(kv.w, hh, ll); sb[AKH + row * APAD + c4 + 3] = hh; sb[AKL + row * APAD + c4 + 3] = ll;
            float4 vv = *(const float4*)(V + baseBH + (size_t)(k0 + row) * DMODEL + c4);
            bsplit(vv.x, hh, ll); sb[AVH + (c4 + 0) * APAD + row] = hh; sb[AVL + (c4 + 0) * APAD + row] = ll;
            bsplit(vv.y, hh, ll); sb[AVH + (c4 + 1) * APAD + row] = hh; sb[AVL + (c4 + 1) * APAD + row] = ll;
            bsplit(vv.z, hh, ll); sb[AVH + (c4 + 2) * APAD + row] = hh; sb[AVL + (c4 + 2) * APAD + row] = ll;
            bsplit(vv.w, hh, ll); sb[AVH + (c4 + 3) * APAD + row] = hh; sb[AVL + (c4 + 3) * APAD + row] = ll;
        }
        if (t < 64) mk[t] = mask[(size_t)b * SEQ + k0 + t];
        __syncthreads();

        // ---- S = Q @ K^T (3-pass) ----
        float S[8][4];
#pragma unroll
        for (int j = 0; j < 8; ++j)
#pragma unroll
            for (int e = 0; e < 4; ++e) S[j][e] = 0.f;
#pragma unroll
        for (int ks = 0; ks < 4; ++ks)
#pragma unroll
            for (int j = 0; j < 8; ++j) {
                uint32_t bh2[2], bl2[2];
                uint32_t ra = sbase + 2 * (AKH + (j * 8 + brw) * APAD + ks * 16 + bcl);
                LDSM_X2(bh2, ra);
                LDSM_X2(bl2, ra + 2 * (AKL - AKH));
                MMA16816(S[j], qh[ks], bh2);
                MMA16816(S[j], ql[ks], bh2);
                MMA16816(S[j], qh[ks], bl2);
            }

        // ---- masked online softmax (fp32, fragment-local) ----
        float ma = -1e30f, mb = -1e30f;
#pragma unroll
        for (int j = 0; j < 8; ++j)
#pragma unroll
            for (int e = 0; e < 4; ++e) {
                int key = j * 8 + tig * 2 + (e & 1);
                float s = mk[key] ? S[j][e] * 0.125f : -1e30f;
                S[j][e] = s;
                if (e < 2) ma = fmaxf(ma, s); else mb = fmaxf(mb, s);
            }
        ma = fmaxf(ma, __shfl_xor_sync(0xffffffffu, ma, 1));
        ma = fmaxf(ma, __shfl_xor_sync(0xffffffffu, ma, 2));
        mb = fmaxf(mb, __shfl_xor_sync(0xffffffffu, mb, 1));
        mb = fmaxf(mb, __shfl_xor_sync(0xffffffffu, mb, 2));

        float mn0 = fmaxf(m0, ma), mn1 = fmaxf(m1, mb);
        float sc0 = __expf(m0 - mn0), sc1 = __expf(m1 - mn1);
#pragma unroll
        for (int d = 0; d < 8; ++d) {
            Oa[d][0] *= sc0; Oa[d][1] *= sc0;
            Oa[d][2] *= sc1; Oa[d][3] *= sc1;
        }
        float ll0 = 0.f, ll1 = 0.f;
#pragma unroll
        for (int j = 0; j < 8; ++j) {
            float p0 = __expf(S[j][0] - mn0);
            float p1 = __expf(S[j][1] - mn0);
            float p2 = __expf(S[j][2] - mn1);
            float p3 = __expf(S[j][3] - mn1);
            S[j][0] = p0; S[j][1] = p1; S[j][2] = p2; S[j][3] = p3;
            ll0 += p0 + p1; ll1 += p2 + p3;
        }
        ll0 += __shfl_xor_sync(0xffffffffu, ll0, 1);
        ll0 += __shfl_xor_sync(0xffffffffu, ll0, 2);
        ll1 += __shfl_xor_sync(0xffffffffu, ll1, 1);
        ll1 += __shfl_xor_sync(0xffffffffu, ll1, 2);
        l0 = l0 * sc0 + ll0;
        l1 = l1 * sc1 + ll1;
        m0 = mn0; m1 = mn1;

        // ---- pack P into A-fragments (register-only) ----
        uint32_t ph[4][4], pl[4][4];
#pragma unroll
        for (int kk = 0; kk < 4; ++kk) {
            packsplit2(S[2 * kk][0],     S[2 * kk][1],     ph[kk][0], pl[kk][0]);
            packsplit2(S[2 * kk][2],     S[2 * kk][3],     ph[kk][1], pl[kk][1]);
            packsplit2(S[2 * kk + 1][0], S[2 * kk + 1][1], ph[kk][2], pl[kk][2]);
            packsplit2(S[2 * kk + 1][2], S[2 * kk + 1][3], ph[kk][3], pl[kk][3]);
        }

        // ---- O += P @ V (3-pass) ----
#pragma unroll
        for (int kk = 0; kk < 4; ++kk)
#pragma unroll
            for (int d = 0; d < 8; ++d) {
                uint32_t vh2[2], vl2[2];
                uint32_t ra = sbase + 2 * (AVH + (d * 8 + brw) * APAD + kk * 16 + bcl);
                LDSM_X2(vh2, ra);
                LDSM_X2(vl2, ra + 2 * (AVL - AVH));
                MMA16816(Oa[d], ph[kk], vh2);
                MMA16816(Oa[d], pl[kk], vh2);
                MMA16816(Oa[d], ph[kk], vl2);
            }
        __syncthreads();
    }

    // Epilogue: normalize, q-mask, write
    const int row0 = q0 + w * 16 + gid;
    const int row1 = row0 + 8;
    const int mq0 = mask[(size_t)b * SEQ + row0];
    const int mq1 = mask[(size_t)b * SEQ + row1];
    const float inv0 = (mq0 != 0 && l0 > 0.f) ? (1.f / l0) : 0.f;
    const float inv1 = (mq1 != 0 && l1 > 0.f) ? (1.f / l1) : 0.f;
#pragma unroll
    for (int d = 0; d < 8; ++d) {
        int col = d * 8 + tig * 2;
        *reinterpret_cast<float2*>(O + baseBH + (size_t)row0 * DMODEL + col) =
            make_float2(Oa[d][0] * inv0, Oa[d][1] * inv0);
        *reinterpret_cast<float2*>(O + baseBH + (size_t)row1 * DMODEL + col) =
            make_float2(Oa[d][2] * inv1, Oa[d][3] * inv1);
    }
}

// ---------------------------------------------------------------------------
// Launch
// ---------------------------------------------------------------------------
extern "C" void kernel_launch(void* const* d_in, const int* in_sizes, int n_in,
                              void* d_out, int out_size)
{
    const float* q    = (const float*)d_in[0];
    const float* k    = (const float*)d_in[1];
    const float* v    = (const float*)d_in[2];
    const int*   mask = (const int*)  d_in[3];
    const float* Wq   = (const float*)d_in[4];
    const float* bq   = (const float*)d_in[5];
    const float* Wk   = (const float*)d_in[6];
    const float* bk   = (const float*)d_in[7];
    const float* Wv   = (const float*)d_in[8];
    const float* bv   = (const float*)d_in[9];
    const float* Wo   = (const float*)d_in[10];
    const float* bo   = (const float*)d_in[11];
    float* out = (float*)d_out;

    float *Qp, *Kp, *Vp, *At;
    __nv_bfloat16 *ah, *al, *wh, *wl;
    cudaGetSymbolAddress((void**)&Qp, g_Qp);
    cudaGetSymbolAddress((void**)&Kp, g_Kp);
    cudaGetSymbolAddress((void**)&Vp, g_Vp);
    cudaGetSymbolAddress((void**)&At, g_At);
    cudaGetSymbolAddress((void**)&ah, g_ah);
    cudaGetSymbolAddress((void**)&al, g_al);
    cudaGetSymbolAddress((void**)&wh, g_wh);
    cudaGetSymbolAddress((void**)&wl, g_wl);

    cudaFuncSetAttribute(gemm_mma_kernel,
                         cudaFuncAttributeMaxDynamicSharedMemorySize, GSM_BYTES);
    cudaFuncSetAttribute(attn_mma_kernel,
                         cudaFuncAttributeMaxDynamicSharedMemorySize, ATT2_SMEM);

    const int nAct4 = MROWS * DMODEL / 4;
    const int nW4   = DMODEL * DMODEL / 4;
    dim3 gGemm(DMODEL / 128, MROWS / 128);      // (8, 64)

    // Q projection
    split_kernel<<<(nAct4 + 255) / 256, 256>>>((const float4*)q, ah, al, nAct4);
    split_kernel<<<(nW4 + 255) / 256, 256>>>((const float4*)Wq, wh, wl, nW4);
    gemm_mma_kernel<<<gGemm, 256, GSM_BYTES>>>(ah, al, wh, wl, bq, Qp);
    // K projection
    split_kernel<<<(nAct4 + 255) / 256, 256>>>((const float4*)k, ah, al, nAct4);
    split_kernel<<<(nW4 + 255) / 256, 256>>>((const float4*)Wk, wh, wl, nW4);
    gemm_mma_kernel<<<gGemm, 256, GSM_BYTES>>>(ah, al, wh, wl, bk, Kp);
    // V projection
    split_kernel<<<(nAct4 + 255) / 256, 256>>>((const float4*)v, ah, al, nAct4);
    split_kernel<<<(nW4 + 255) / 256, 256>>>((const float4*)Wv, wh, wl, nW4);
    gemm_mma_kernel<<<gGemm, 256, GSM_BYTES>>>(ah, al, wh, wl, bv, Vp);

    // Attention (tensor-core)
    dim3 gAttn(SEQ / 128, NH, BSZ);             // (16, 16, 4)
    attn_mma_kernel<<<gAttn, 256, ATT2_SMEM>>>(Qp, Kp, Vp, mask, At);

    // Output projection
    split_kernel<<<(nAct4 + 255) / 256, 256>>>((const float4*)At, ah, al, nAct4);
    split_kernel<<<(nW4 + 255) / 256, 256>>>((const float4*)Wo, wh, wl, nW4);
    gemm_mma_kernel<<<gGemm, 256, GSM_BYTES>>>(ah, al, wh, wl, bo, out);
}

// round 16
// speedup vs baseline: 4.2126x; 1.1668x over previous
#include <cuda_runtime.h>
#include <cuda_bf16.h>
#include <cstdint>
#include <math.h>

#define BSZ 4
#define SEQ 2048
#define DMODEL 1024
#define NH 16
#define DKH 64
#define MROWS (BSZ * SEQ)   // 8192

// ---------------------------------------------------------------------------
// Scratch (device globals: allocation-free rule)
// ---------------------------------------------------------------------------
__device__ float g_Qp[(size_t)MROWS * DMODEL];
__device__ float g_Kp[(size_t)MROWS * DMODEL];
__device__ float g_Vp[(size_t)MROWS * DMODEL];
__device__ float g_At[(size_t)MROWS * DMODEL];

// ---------------------------------------------------------------------------
// Warp MMA helpers (PTX sm_80-level: valid under virtual compute_103)
// ---------------------------------------------------------------------------
__device__ __forceinline__ uint32_t smem_u32(const void* p) {
    uint32_t a;
    asm("{ .reg .u64 t; cvta.to.shared.u64 t, %1; cvt.u32.u64 %0, t; }"
        : "=r"(a) : "l"(p));
    return a;
}
#define LDSM_X4(r, addr) \
    asm volatile("ldmatrix.sync.aligned.m8n8.x4.shared.b16 {%0,%1,%2,%3}, [%4];" \
        : "=r"((r)[0]), "=r"((r)[1]), "=r"((r)[2]), "=r"((r)[3]) : "r"(addr))
#define LDSM_X2(r, addr) \
    asm volatile("ldmatrix.sync.aligned.m8n8.x2.shared.b16 {%0,%1}, [%2];" \
        : "=r"((r)[0]), "=r"((r)[1]) : "r"(addr))
#define MMA16816(c, a, b) \
    asm volatile("mma.sync.aligned.m16n8k16.row.col.f32.bf16.bf16.f32 " \
        "{%0,%1,%2,%3}, {%4,%5,%6,%7}, {%8,%9}, {%0,%1,%2,%3};" \
        : "+f"((c)[0]), "+f"((c)[1]), "+f"((c)[2]), "+f"((c)[3]) \
        : "r"((a)[0]), "r"((a)[1]), "r"((a)[2]), "r"((a)[3]), \
          "r"((b)[0]), "r"((b)[1]))

// Split x into bf16 hi/lo
__device__ __forceinline__ void bsplit(float x, __nv_bfloat16& h, __nv_bfloat16& l) {
    h = __float2bfloat16(x);
    l = __float2bfloat16(x - __bfloat162float(h));
}
// Pack pair (x->low half, y->high half) with hi/lo split
__device__ __forceinline__ void packsplit2(float x, float y, uint32_t& hi, uint32_t& lo) {
    __nv_bfloat162 H = __floats2bfloat162_rn(x, y);
    float rx = x - __bfloat162float(H.x);
    float ry = y - __bfloat162float(H.y);
    __nv_bfloat162 L = __floats2bfloat162_rn(rx, ry);
    hi = *reinterpret_cast<uint32_t*>(&H);
    lo = *reinterpret_cast<uint32_t*>(&L);
}

// ---------------------------------------------------------------------------
// HMMA GEMM with FUSED fp32->hi/lo split in the staging path.
// C[8192,1024] = A[M,K] @ B[N,K]^T + bias. 3-pass compensated (AhBh+AhBl+AlBh).
// Reads fp32 A/B directly (same 4B/elem as hi+lo bf16) -> no split kernels.
// ---------------------------------------------------------------------------
#define GPAD 40
#define GTILE (128 * GPAD)
#define GSTAGE (4 * GTILE)               // Ah,Al,Bh,Bl
#define GSM_BYTES (2 * GSTAGE * 2)       // 2 stages -> 81920 B

__global__ __launch_bounds__(256) void gemm_mma_kernel(
    const float* __restrict__ A, const float* __restrict__ B,
    const float* __restrict__ bias, float* __restrict__ C)
{
    extern __shared__ __align__(16) __nv_bfloat16 sm[];
    const int tid  = threadIdx.x;
    const int wid  = tid >> 5;
    const int lane = tid & 31;
    const int brow = blockIdx.y * 128, bcol = blockIdx.x * 128;
    const int wm   = (wid & 1) * 64;
    const int wn   = (wid >> 1) * 32;

    const uint32_t sbase = smem_u32(sm);
    const int lr0 = tid >> 2, ls0 = (tid & 3) * 8;   // 8 floats per thread per row

    // Convert 8 fp32 -> hi/lo uint4 and store to tile (elem offsets)
    auto cvst = [&](__nv_bfloat16* dst, int tileOff, int row, float4 x0, float4 x1) {
        uint32_t h0, h1, h2, h3, l0, l1, l2, l3;
        packsplit2(x0.x, x0.y, h0, l0); packsplit2(x0.z, x0.w, h1, l1);
        packsplit2(x1.x, x1.y, h2, l2); packsplit2(x1.z, x1.w, h3, l3);
        *reinterpret_cast<uint4*>(dst + tileOff + row * GPAD + ls0) =
            make_uint4(h0, h1, h2, h3);
        *reinterpret_cast<uint4*>(dst + tileOff + GTILE + row * GPAD + ls0) =
            make_uint4(l0, l1, l2, l3);
    };

    // Prologue: chunk 0 -> stage 0
#pragma unroll
    for (int s = 0; s < 2; ++s) {
        const float* src = s ? B : A;
        const int rbase = s ? bcol : brow;
#pragma unroll
        for (int it = 0; it < 2; ++it) {
            int row = lr0 + it * 64;
            const float* p = src + (size_t)(rbase + row) * DMODEL + ls0;
            float4 x0 = *reinterpret_cast<const float4*>(p);
            float4 x1 = *reinterpret_cast<const float4*>(p + 4);
            cvst(sm, s * 2 * GTILE, row, x0, x1);
        }
    }
    __syncthreads();

    float acc[4][4][4];
#pragma unroll
    for (int i = 0; i < 4; ++i)
#pragma unroll
        for (int j = 0; j < 4; ++j)
#pragma unroll
            for (int e = 0; e < 4; ++e) acc[i][j][e] = 0.f;

    const int arow = wm + (lane & 15);
    const int acol = (lane >> 4) * 8;
    const int brw  = wn + (lane & 7);
    const int bcl  = ((lane >> 3) & 1) * 8;

    for (int c = 0; c < DMODEL / 32; ++c) {
        const int st = c & 1;
        // Prefetch next chunk (fp32) into registers; hidden under MMA
        float4 nxt[8];
        if (c + 1 < DMODEL / 32) {
#pragma unroll
            for (int s = 0; s < 2; ++s) {
                const float* src = s ? B : A;
                const int rbase = s ? bcol : brow;
#pragma unroll
                for (int it = 0; it < 2; ++it) {
                    int row = lr0 + it * 64;
                    const float* p = src + (size_t)(rbase + row) * DMODEL
                                     + (c + 1) * 32 + ls0;
                    nxt[s * 4 + it * 2 + 0] = *reinterpret_cast<const float4*>(p);
                    nxt[s * 4 + it * 2 + 1] = *reinterpret_cast<const float4*>(p + 4);
                }
            }
        }

        const uint32_t stOff = sbase + st * (GSTAGE * 2);
#pragma unroll
        for (int ks = 0; ks < 2; ++ks) {
            uint32_t ah[4][4], al[4][4], bh[4][2], bl[4][2];
#pragma unroll
            for (int mt = 0; mt < 4; ++mt) {
                uint32_t ra = stOff + 2 * ((arow + mt * 16) * GPAD + ks * 16 + acol);
                LDSM_X4(ah[mt], ra);
                LDSM_X4(al[mt], ra + 2 * GTILE);
            }
#pragma unroll
            for (int nt = 0; nt < 4; ++nt) {
                uint32_t rbA = stOff + 2 * (2 * GTILE + (brw + nt * 8) * GPAD + ks * 16 + bcl);
                LDSM_X2(bh[nt], rbA);
                LDSM_X2(bl[nt], rbA + 2 * GTILE);
            }
#pragma unroll
            for (int mt = 0; mt < 4; ++mt)
#pragma unroll
                for (int nt = 0; nt < 4; ++nt) {
                    MMA16816(acc[mt][nt], ah[mt], bh[nt]);
                    MMA16816(acc[mt][nt], ah[mt], bl[nt]);
                    MMA16816(acc[mt][nt], al[mt], bh[nt]);
                }
        }

        if (c + 1 < DMODEL / 32) {
            __nv_bfloat16* dst = sm + (st ^ 1) * GSTAGE;
#pragma unroll
            for (int s = 0; s < 2; ++s)
#pragma unroll
                for (int it = 0; it < 2; ++it) {
                    int row = lr0 + it * 64;
                    cvst(dst, s * 2 * GTILE, row,
                         nxt[s * 4 + it * 2 + 0], nxt[s * 4 + it * 2 + 1]);
                }
        }
        __syncthreads();
    }

    const int gid = lane >> 2, tig = lane & 3;
#pragma unroll
    for (int mt = 0; mt < 4; ++mt)
#pragma unroll
        for (int nt = 0; nt < 4; ++nt) {
            int col = bcol + wn + nt * 8 + tig * 2;
            float2 bv = *reinterpret_cast<const float2*>(bias + col);
            int row0 = brow + wm + mt * 16 + gid;
            float2 o0 = make_float2(acc[mt][nt][0] + bv.x, acc[mt][nt][1] + bv.y);
            float2 o1 = make_float2(acc[mt][nt][2] + bv.x, acc[mt][nt][3] + bv.y);
            *reinterpret_cast<float2*>(C + (size_t)row0 * DMODEL + col) = o0;
            *reinterpret_cast<float2*>(C + (size_t)(row0 + 8) * DMODEL + col) = o1;
        }
}

// ---------------------------------------------------------------------------
// MMA flash attention (verified R14) + software-pipelined K/V staging:
// next tile's gmem loads are issued right after the staging sync and consumed
// at the next iteration's convert+store, hiding DRAM latency under the MMAs.
// ---------------------------------------------------------------------------
#define APAD 72
#define AQH 0
#define AQL (128 * APAD)
#define AKH (2 * 128 * APAD)
#define AKL (AKH + 64 * APAD)
#define AVH (AKL + 64 * APAD)
#define AVL (AVH + 64 * APAD)
#define AEND (AVL + 64 * APAD)
#define ATT2_SMEM (AEND * 2 + 64 * 4)     // 73984 B

__global__ __launch_bounds__(256, 1) void attn_mma_kernel(
    const float* __restrict__ Q, const float* __restrict__ K,
    const float* __restrict__ V, const int* __restrict__ mask,
    float* __restrict__ O)
{
    extern __shared__ __align__(16) __nv_bfloat16 sb[];
    int* mk = (int*)(sb + AEND);
    const uint32_t sbase = smem_u32(sb);

    const int t = threadIdx.x, w = t >> 5, lane = t & 31;
    const int b = blockIdx.z, h = blockIdx.y, q0 = blockIdx.x * 128;
    const size_t baseBH = (size_t)b * SEQ * DMODEL + (size_t)h * DKH;

    // Stage Q tile (128x64) as hi/lo bf16
#pragma unroll
    for (int it = 0; it < 8; ++it) {
        int f = t + it * 256;
        int row = f >> 4, c4 = (f & 15) * 4;
        float4 v = *(const float4*)(Q + baseBH + (size_t)(q0 + row) * DMODEL + c4);
        __nv_bfloat16 hh, ll;
        bsplit(v.x, hh, ll); sb[AQH + row * APAD + c4 + 0] = hh; sb[AQL + row * APAD + c4 + 0] = ll;
        bsplit(v.y, hh, ll); sb[AQH + row * APAD + c4 + 1] = hh; sb[AQL + row * APAD + c4 + 1] = ll;
        bsplit(v.z, hh, ll); sb[AQH + row * APAD + c4 + 2] = hh; sb[AQL + row * APAD + c4 + 2] = ll;
        bsplit(v.w, hh, ll); sb[AQH + row * APAD + c4 + 3] = hh; sb[AQL + row * APAD + c4 + 3] = ll;
    }
    __syncthreads();

    // Q fragments (held across the whole loop)
    uint32_t qh[4][4], ql[4][4];
    const int arow = w * 16 + (lane & 15);
    const int acol = (lane >> 4) * 8;
#pragma unroll
    for (int ks = 0; ks < 4; ++ks) {
        uint32_t ra = sbase + 2 * (AQH + arow * APAD + ks * 16 + acol);
        LDSM_X4(qh[ks], ra);
        LDSM_X4(ql[ks], ra + 2 * (AQL - AQH));
    }

    const int gid = lane >> 2, tig = lane & 3;
    const int brw = lane & 7;
    const int bcl = ((lane >> 3) & 1) * 8;

    float m0 = -1e30f, m1 = -1e30f, l0 = 0.f, l1 = 0.f;
    float Oa[8][4];
#pragma unroll
    for (int d = 0; d < 8; ++d)
#pragma unroll
        for (int e = 0; e < 4; ++e) Oa[d][e] = 0.f;

    // Prefetch tile 0 (K and V) into registers
    float4 kr[4], vr[4];
#pragma unroll
    for (int it = 0; it < 4; ++it) {
        int f = t + it * 256;
        int row = f >> 4, c4 = (f & 15) * 4;
        kr[it] = *(const float4*)(K + baseBH + (size_t)row * DMODEL + c4);
        vr[it] = *(const float4*)(V + baseBH + (size_t)row * DMODEL + c4);
    }

    for (int k0 = 0; k0 < SEQ; k0 += 64) {
        // Convert + store prefetched K (row-major) and V (transposed) hi/lo
#pragma unroll
        for (int it = 0; it < 4; ++it) {
            int f = t + it * 256;
            int row = f >> 4, c4 = (f & 15) * 4;   // row = key, c4 = dk
            __nv_bfloat16 hh, ll;
            bsplit(kr[it].x, hh, ll); sb[AKH + row * APAD + c4 + 0] = hh; sb[AKL + row * APAD + c4 + 0] = ll;
            bsplit(kr[it].y, hh, ll); sb[AKH + row * APAD + c4 + 1] = hh; sb[AKL + row * APAD + c4 + 1] = ll;
            bsplit(kr[it].z, hh, ll); sb[AKH + row * APAD + c4 + 2] = hh; sb[AKL + row * APAD + c4 + 2] = ll;
            bsplit(kr[it].w, hh, ll); sb[AKH + row * APAD + c4 + 3] = hh; sb[AKL + row * APAD + c4 + 3] = ll;
            bsplit(vr[it].x, hh, ll); sb[AVH + (c4 + 0) * APAD + row] = hh; sb[AVL + (c4 + 0) * APAD + row] = ll;
            bsplit(vr[it].y, hh, ll); sb[AVH + (c4 + 1) * APAD + row] = hh; sb[AVL + (c4 + 1) * APAD + row] = ll;
            bsplit(vr[it].z, hh, ll); sb[AVH + (c4 + 2) * APAD + row] = hh; sb[AVL + (c4 + 2) * APAD + row] = ll;
            bsplit(vr[it].w, hh, ll); sb[AVH + (c4 + 3) * APAD + row] = hh; sb[AVL + (c4 + 3) * APAD + row] = ll;
        }
        if (t < 64) mk[t] = mask[(size_t)b * SEQ + k0 + t];
        __syncthreads();

        // Issue next tile's loads now; consumed after the MMA section
        if (k0 + 64 < SEQ) {
#pragma unroll
            for (int it = 0; it < 4; ++it) {
                int f = t + it * 256;
                int row = f >> 4, c4 = (f & 15) * 4;
                kr[it] = *(const float4*)(K + baseBH + (size_t)(k0 + 64 + row) * DMODEL + c4);
                vr[it] = *(const float4*)(V + baseBH + (size_t)(k0 + 64 + row) * DMODEL + c4);
            }
        }

        // ---- S = Q @ K^T (3-pass) ----
        float S[8][4];
#pragma unroll
        for (int j = 0; j < 8; ++j)
#pragma unroll
            for (int e = 0; e < 4; ++e) S[j][e] = 0.f;
#pragma unroll
        for (int ks = 0; ks < 4; ++ks)
#pragma unroll
            for (int j = 0; j < 8; ++j) {
                uint32_t bh2[2], bl2[2];
                uint32_t ra = sbase + 2 * (AKH + (j * 8 + brw) * APAD + ks * 16 + bcl);
                LDSM_X2(bh2, ra);
                LDSM_X2(bl2, ra + 2 * (AKL - AKH));
                MMA16816(S[j], qh[ks], bh2);
                MMA16816(S[j], ql[ks], bh2);
                MMA16816(S[j], qh[ks], bl2);
            }

        // ---- masked online softmax (fp32, fragment-local) ----
        float ma = -1e30f, mb = -1e30f;
#pragma unroll
        for (int j = 0; j < 8; ++j)
#pragma unroll
            for (int e = 0; e < 4; ++e) {
                int key = j * 8 + tig * 2 + (e & 1);
                float s = mk[key] ? S[j][e] * 0.125f : -1e30f;
                S[j][e] = s;
                if (e < 2) ma = fmaxf(ma, s); else mb = fmaxf(mb, s);
            }
        ma = fmaxf(ma, __shfl_xor_sync(0xffffffffu, ma, 1));
        ma = fmaxf(ma, __shfl_xor_sync(0xffffffffu, ma, 2));
        mb = fmaxf(mb, __shfl_xor_sync(0xffffffffu, mb, 1));
        mb = fmaxf(mb, __shfl_xor_sync(0xffffffffu, mb, 2));

        float mn0 = fmaxf(m0, ma), mn1 = fmaxf(m1, mb);
        float sc0 = __expf(m0 - mn0), sc1 = __expf(m1 - mn1);
#pragma unroll
        for (int d = 0; d < 8; ++d) {
            Oa[d][0] *= sc0; Oa[d][1] *= sc0;
            Oa[d][2] *= sc1; Oa[d][3] *= sc1;
        }
        float ll0 = 0.f, ll1 = 0.f;
#pragma unroll
        for (int j = 0; j < 8; ++j) {
            float p0 = __expf(S[j][0] - mn0);
            float p1 = __expf(S[j][1] - mn0);
            float p2 = __expf(S[j][2] - mn1);
            float p3 = __expf(S[j][3] - mn1);
            S[j][0] = p0; S[j][1] = p1; S[j][2] = p2; S[j][3] = p3;
            ll0 += p0 + p1; ll1 += p2 + p3;
        }
        ll0 += __shfl_xor_sync(0xffffffffu, ll0, 1);
        ll0 += __shfl_xor_sync(0xffffffffu, ll0, 2);
        ll1 += __shfl_xor_sync(0xffffffffu, ll1, 1);
        ll1 += __shfl_xor_sync(0xffffffffu, ll1, 2);
        l0 = l0 * sc0 + ll0;
        l1 = l1 * sc1 + ll1;
        m0 = mn0; m1 = mn1;

        // ---- pack P into A-fragments (register-only) ----
        uint32_t ph[4][4], pl[4][4];
#pragma unroll
        for (int kk = 0; kk < 4; ++kk) {
            packsplit2(S[2 * kk][0],     S[2 * kk][1],     ph[kk][0], pl[kk][0]);
            packsplit2(S[2 * kk][2],     S[2 * kk][3],     ph[kk][1], pl[kk][1]);
            packsplit2(S[2 * kk + 1][0], S[2 * kk + 1][1], ph[kk][2], pl[kk][2]);
            packsplit2(S[2 * kk + 1][2], S[2 * kk + 1][3], ph[kk][3], pl[kk][3]);
        }

        // ---- O += P @ V (3-pass) ----
#pragma unroll
        for (int kk = 0; kk < 4; ++kk)
#pragma unroll
            for (int d = 0; d < 8; ++d) {
                uint32_t vh2[2], vl2[2];
                uint32_t ra = sbase + 2 * (AVH + (d * 8 + brw) * APAD + kk * 16 + bcl);
                LDSM_X2(vh2, ra);
                LDSM_X2(vl2, ra + 2 * (AVL - AVH));
                MMA16816(Oa[d], ph[kk], vh2);
                MMA16816(Oa[d], pl[kk], vh2);
                MMA16816(Oa[d], ph[kk], vl2);
            }
        __syncthreads();
    }

    // Epilogue: normalize, q-mask, write
    const int row0 = q0 + w * 16 + gid;
    const int row1 = row0 + 8;
    const int mq0 = mask[(size_t)b * SEQ + row0];
    const int mq1 = mask[(size_t)b * SEQ + row1];
    const float inv0 = (mq0 != 0 && l0 > 0.f) ? (1.f / l0) : 0.f;
    const float inv1 = (mq1 != 0 && l1 > 0.f) ? (1.f / l1) : 0.f;
#pragma unroll
    for (int d = 0; d < 8; ++d) {
        int col = d * 8 + tig * 2;
        *reinterpret_cast<float2*>(O + baseBH + (size_t)row0 * DMODEL + col) =
            make_float2(Oa[d][0] * inv0, Oa[d][1] * inv0);
        *reinterpret_cast<float2*>(O + baseBH + (size_t)row1 * DMODEL + col) =
            make_float2(Oa[d][2] * inv1, Oa[d][3] * inv1);
    }
}

// ---------------------------------------------------------------------------
// Launch
// ---------------------------------------------------------------------------
extern "C" void kernel_launch(void* const* d_in, const int* in_sizes, int n_in,
                              void* d_out, int out_size)
{
    const float* q    = (const float*)d_in[0];
    const float* k    = (const float*)d_in[1];
    const float* v    = (const float*)d_in[2];
    const int*   mask = (const int*)  d_in[3];
    const float* Wq   = (const float*)d_in[4];
    const float* bq   = (const float*)d_in[5];
    const float* Wk   = (const float*)d_in[6];
    const float* bk   = (const float*)d_in[7];
    const float* Wv   = (const float*)d_in[8];
    const float* bv   = (const float*)d_in[9];
    const float* Wo   = (const float*)d_in[10];
    const float* bo   = (const float*)d_in[11];
    float* out = (float*)d_out;

    float *Qp, *Kp, *Vp, *At;
    cudaGetSymbolAddress((void**)&Qp, g_Qp);
    cudaGetSymbolAddress((void**)&Kp, g_Kp);
    cudaGetSymbolAddress((void**)&Vp, g_Vp);
    cudaGetSymbolAddress((void**)&At, g_At);

    cudaFuncSetAttribute(gemm_mma_kernel,
                         cudaFuncAttributeMaxDynamicSharedMemorySize, GSM_BYTES);
    cudaFuncSetAttribute(attn_mma_kernel,
                         cudaFuncAttributeMaxDynamicSharedMemorySize, ATT2_SMEM);

    dim3 gGemm(DMODEL / 128, MROWS / 128);      // (8, 64)

    // Projections (split fused into GEMM staging)
    gemm_mma_kernel<<<gGemm, 256, GSM_BYTES>>>(q, Wq, bq, Qp);
    gemm_mma_kernel<<<gGemm, 256, GSM_BYTES>>>(k, Wk, bk, Kp);
    gemm_mma_kernel<<<gGemm, 256, GSM_BYTES>>>(v, Wv, bv, Vp);

    // Attention (tensor-core, pipelined staging)
    dim3 gAttn(SEQ / 128, NH, BSZ);             // (16, 16, 4)
    attn_mma_kernel<<<gAttn, 256, ATT2_SMEM>>>(Qp, Kp, Vp, mask, At);

    // Output projection
    gemm_mma_kernel<<<gGemm, 256, GSM_BYTES>>>(At, Wo, bo, out);
}